// round 6
// baseline (speedup 1.0000x reference)
#include <cuda_runtime.h>
#include <cstdint>

// out[j]     = dot(X[r1(j)], p), r1(j) = inds1[2j]*28 + inds1[2j+1], j in [0,100)
// out[100+j] = dot(Y[r2(j)], p)
// 200 dots x 2 segments = 400 CTAs. Each CTA bulk-copies its 64KB half-row into
// 4 x 16KB SMEM buffers via cp.async.bulk (all 4 issued up front -> 64KB in
// flight per CTA, no register-MLP limit), then dots against p (LDG, L2-hot).
// Per-dot atomic finisher sums the 2 partials in fixed order.

#define Q          32768
#define W_DIM      28
#define NDOTS      200
#define NSEG       2
#define NBLK       (NDOTS * NSEG)      // 400
#define NT         256
#define SEG_FL     (Q / NSEG)          // 16384 floats per segment
#define NCH        4
#define CH_FL      (SEG_FL / NCH)      // 4096 floats per chunk
#define CH_BYTES   (CH_FL * 4)         // 16384 B
#define CH_F4      (CH_FL / 4)         // 1024 float4
#define SMEM_DATA  (NCH * CH_BYTES)    // 65536 B
#define SMEM_TOTAL (SMEM_DATA + 64)    // + mbarriers

__device__ float        g_partial[NBLK];
__device__ unsigned int g_cnt[NDOTS];

__device__ __forceinline__ uint32_t smem_u32(const void* ptr) {
    uint32_t addr;
    asm("{ .reg .u64 t; cvta.to.shared.u64 t, %1; cvt.u32.u64 %0, t; }"
        : "=r"(addr) : "l"(ptr));
    return addr;
}

__device__ __forceinline__ float dot4(float4 a, float4 b) {
    return a.x * b.x + a.y * b.y + a.z * b.z + a.w * b.w;
}

__global__ __launch_bounds__(NT)
void dot_bulk_kernel(const float* __restrict__ X,
                     const float* __restrict__ Y,
                     const float* __restrict__ p,
                     const int*   __restrict__ inds1,
                     const int*   __restrict__ inds2,
                     float* __restrict__ out)
{
    extern __shared__ char smem[];
    const uint32_t data_base = smem_u32(smem);
    const uint32_t mbar_base = data_base + SMEM_DATA;

    const int b   = blockIdx.x;         // 0..399
    const int j   = b >> 1;             // dot 0..199
    const int seg = b & 1;

    const bool second = (j >= 100);
    const int jj = second ? (j - 100) : j;
    const int* __restrict__ inds = second ? inds2 : inds1;
    const float* __restrict__ M  = second ? Y : X;

    const int r = inds[2 * jj] * W_DIM + inds[2 * jj + 1];
    const float* src = M + (size_t)r * Q + seg * SEG_FL;

    // Init 4 mbarriers, fence for async proxy, then issue all 4 bulk copies.
    if (threadIdx.x == 0) {
        #pragma unroll
        for (int c = 0; c < NCH; c++)
            asm volatile("mbarrier.init.shared::cta.b64 [%0], 1;"
                         :: "r"(mbar_base + c * 8) : "memory");
        asm volatile("fence.proxy.async.shared::cta;" ::: "memory");
        #pragma unroll
        for (int c = 0; c < NCH; c++) {
            uint32_t mb = mbar_base + c * 8;
            asm volatile("mbarrier.arrive.expect_tx.shared::cta.b64 _, [%0], %1;"
                         :: "r"(mb), "r"((uint32_t)CH_BYTES) : "memory");
            asm volatile(
                "cp.async.bulk.shared::cta.global.mbarrier::complete_tx::bytes "
                "[%0], [%1], %2, [%3];"
                :: "r"(data_base + c * CH_BYTES),
                   "l"(src + c * CH_FL),
                   "r"((uint32_t)CH_BYTES),
                   "r"(mb)
                : "memory");
        }
    }
    __syncthreads();   // all threads see initialized barriers

    const float4* __restrict__ pv =
        reinterpret_cast<const float4*>(p) + seg * (SEG_FL / 4);

    float sum = 0.0f;
    #pragma unroll
    for (int c = 0; c < NCH; c++) {
        // Prefetch p for this chunk (L2-hot) BEFORE waiting on the barrier.
        float4 pb0 = pv[c * CH_F4 + threadIdx.x];
        float4 pb1 = pv[c * CH_F4 + threadIdx.x +     NT];
        float4 pb2 = pv[c * CH_F4 + threadIdx.x + 2 * NT];
        float4 pb3 = pv[c * CH_F4 + threadIdx.x + 3 * NT];

        // Wait for chunk c (parity 0, barriers freshly initialized each launch)
        asm volatile(
            "{\n\t"
            ".reg .pred P;\n\t"
            "W%=:\n\t"
            "mbarrier.try_wait.parity.acquire.cta.shared::cta.b64 P, [%0], 0;\n\t"
            "@P bra D%=;\n\t"
            "bra W%=;\n\t"
            "D%=:\n\t"
            "}"
            :: "r"(mbar_base + c * 8) : "memory");

        const float4* bb = reinterpret_cast<const float4*>(smem + c * CH_BYTES);
        float4 a0 = bb[threadIdx.x];
        float4 a1 = bb[threadIdx.x +     NT];
        float4 a2 = bb[threadIdx.x + 2 * NT];
        float4 a3 = bb[threadIdx.x + 3 * NT];
        sum += dot4(a0, pb0);
        sum += dot4(a1, pb1);
        sum += dot4(a2, pb2);
        sum += dot4(a3, pb3);
    }

    // warp reduce
    #pragma unroll
    for (int off = 16; off > 0; off >>= 1)
        sum += __shfl_xor_sync(0xFFFFFFFFu, sum, off);

    __shared__ float warp_sums[NT / 32];
    const int lane = threadIdx.x & 31;
    const int wid  = threadIdx.x >> 5;
    if (lane == 0) warp_sums[wid] = sum;
    __syncthreads();

    if (threadIdx.x == 0) {
        float s = warp_sums[0];
        #pragma unroll
        for (int w = 1; w < NT / 32; w++) s += warp_sums[w];

        g_partial[j * NSEG + seg] = s;
        __threadfence();
        unsigned int t = atomicAdd(&g_cnt[j], 1u);
        if (t == NSEG - 1) {
            __threadfence();
            const volatile float* gp = g_partial + j * NSEG;
            out[j] = gp[0] + gp[1];     // fixed order -> deterministic
            g_cnt[j] = 0;               // reset for next graph replay
        }
    }
}

extern "C" void kernel_launch(void* const* d_in, const int* in_sizes, int n_in,
                              void* d_out, int out_size)
{
    const float* X   = (const float*)d_in[0];
    const float* Y   = (const float*)d_in[1];
    const float* p   = (const float*)d_in[2];
    const int* inds1 = (const int*)d_in[3];
    const int* inds2 = (const int*)d_in[4];
    float* out       = (float*)d_out;

    static int attr_done = 0;
    if (!attr_done) {
        cudaFuncSetAttribute(dot_bulk_kernel,
                             cudaFuncAttributeMaxDynamicSharedMemorySize,
                             SMEM_TOTAL);
        attr_done = 1;
    }

    dot_bulk_kernel<<<NBLK, NT, SMEM_TOTAL>>>(X, Y, p, inds1, inds2, out);
}

// round 7
// speedup vs baseline: 1.0179x; 1.0179x over previous
#include <cuda_runtime.h>

// out[j]     = dot(X[r1(j)], p), r1(j) = inds1[2j]*28 + inds1[2j+1], j in [0,100)
// out[100+j] = dot(Y[r2(j)], p)
// R2's fast main loop (200 dots x 8 segments = 1600 blocks, 8 front-batched
// independent LDG.128 per thread) + SPREAD per-dot finisher: 200 counters,
// only 8 CTAs contend per counter; 8th arriver sums partials in fixed order.

#define Q       32768
#define QV      (Q / 4)        // 8192 float4 per row
#define SPLIT   8
#define SEG     (QV / SPLIT)   // 1024 float4 per block
#define NT      256
#define W_DIM   28
#define NDOTS   200
#define NBLK    (NDOTS * SPLIT)  // 1600

__device__ float        g_partial[NBLK];
__device__ unsigned int g_cnt[NDOTS];   // zero-init; finisher resets -> replay-safe

__device__ __forceinline__ float dot4(float4 a, float4 b) {
    return a.x * b.x + a.y * b.y + a.z * b.z + a.w * b.w;
}

__global__ __launch_bounds__(NT)
void dot_split_kernel(const float* __restrict__ X,
                      const float* __restrict__ Y,
                      const float* __restrict__ p,
                      const int*   __restrict__ inds1,
                      const int*   __restrict__ inds2,
                      float* __restrict__ out)
{
    const int b   = blockIdx.x;          // 0..1599
    const int j   = b >> 3;              // dot index 0..199
    const int seg = b & (SPLIT - 1);     // segment 0..7

    const bool second = (j >= 100);
    const int jj = second ? (j - 100) : j;
    const int* __restrict__ inds = second ? inds2 : inds1;
    const float* __restrict__ M  = second ? Y : X;

    const int r = inds[2 * jj] * W_DIM + inds[2 * jj + 1];

    const float4* __restrict__ row = reinterpret_cast<const float4*>(M + (size_t)r * Q);
    const float4* __restrict__ pv  = reinterpret_cast<const float4*>(p);

    const int i0 = seg * SEG + threadIdx.x;

    // 8 independent LDG.128 in flight (exactly the R2 phase-1 shape)
    float4 a0 = row[i0];
    float4 a1 = row[i0 +     NT];
    float4 a2 = row[i0 + 2 * NT];
    float4 a3 = row[i0 + 3 * NT];
    float4 b0 = pv [i0];
    float4 b1 = pv [i0 +     NT];
    float4 b2 = pv [i0 + 2 * NT];
    float4 b3 = pv [i0 + 3 * NT];

    float sum = dot4(a0, b0);
    sum += dot4(a1, b1);
    sum += dot4(a2, b2);
    sum += dot4(a3, b3);

    // warp reduce
    #pragma unroll
    for (int off = 16; off > 0; off >>= 1)
        sum += __shfl_xor_sync(0xFFFFFFFFu, sum, off);

    __shared__ float warp_sums[NT / 32];
    const int lane = threadIdx.x & 31;
    const int wid  = threadIdx.x >> 5;
    if (lane == 0) warp_sums[wid] = sum;
    __syncthreads();

    if (threadIdx.x == 0) {
        float s = warp_sums[0];
        #pragma unroll
        for (int w = 1; w < NT / 32; w++) s += warp_sums[w];

        g_partial[j * SPLIT + seg] = s;
        __threadfence();                             // publish partial
        unsigned int t = atomicAdd(&g_cnt[j], 1u);   // 200 spread addresses
        if (t == SPLIT - 1) {
            __threadfence();                         // acquire others' partials
            const volatile float* gp = g_partial + j * SPLIT;
            float acc = gp[0];                       // fixed order -> deterministic
            #pragma unroll
            for (int k = 1; k < SPLIT; k++) acc += gp[k];
            out[j] = acc;
            g_cnt[j] = 0;                            // reset for next graph replay
        }
    }
}

extern "C" void kernel_launch(void* const* d_in, const int* in_sizes, int n_in,
                              void* d_out, int out_size)
{
    const float* X   = (const float*)d_in[0];
    const float* Y   = (const float*)d_in[1];
    const float* p   = (const float*)d_in[2];
    const int* inds1 = (const int*)d_in[3];
    const int* inds2 = (const int*)d_in[4];
    float* out       = (float*)d_out;

    dot_split_kernel<<<NBLK, NT>>>(X, Y, p, inds1, inds2, out);
}

// round 8
// speedup vs baseline: 1.2620x; 1.2399x over previous
#include <cuda_runtime.h>

// out[j]     = dot(X[r1(j)], p), r1(j) = inds1[2j]*28 + inds1[2j+1], j in [0,100)
// out[100+j] = dot(Y[r2(j)], p)
// Minimal-overhead structure: one block per dot (200 blocks x 1024 threads),
// direct out write, no atomics/fences/partials. Two explicit batches of 8
// independent LDG.128 per thread (MLP=8); launch_bounds(1024,1) lifts the
// 32-reg cap that serialized R1's loads.

#define Q      32768
#define QV     (Q / 4)      // 8192 float4 per row
#define NT     1024
#define W_DIM  28
#define NDOTS  200

__device__ __forceinline__ float dot4(float4 a, float4 b) {
    return a.x * b.x + a.y * b.y + a.z * b.z + a.w * b.w;
}

__global__ __launch_bounds__(NT, 1)
void gathered_dot_kernel(const float* __restrict__ X,
                         const float* __restrict__ Y,
                         const float* __restrict__ p,
                         const int*   __restrict__ inds1,
                         const int*   __restrict__ inds2,
                         float* __restrict__ out)
{
    const int j = blockIdx.x;            // 0..199
    const bool second = (j >= 100);
    const int jj = second ? (j - 100) : j;
    const int* __restrict__ inds = second ? inds2 : inds1;
    const float* __restrict__ M  = second ? Y : X;

    const float4* __restrict__ pv = reinterpret_cast<const float4*>(p);
    const int i0 = threadIdx.x;

    // Start p loads for batch 0 immediately (independent of inds).
    float4 p0 = pv[i0];
    float4 p1 = pv[i0 +     NT];
    float4 p2 = pv[i0 + 2 * NT];
    float4 p3 = pv[i0 + 3 * NT];

    const int r = inds[2 * jj] * W_DIM + inds[2 * jj + 1];
    const float4* __restrict__ row = reinterpret_cast<const float4*>(M + (size_t)r * Q);

    // Batch 0: 4 independent row loads.
    float4 a0 = row[i0];
    float4 a1 = row[i0 +     NT];
    float4 a2 = row[i0 + 2 * NT];
    float4 a3 = row[i0 + 3 * NT];

    // Batch 1 loads issued before consuming batch 0.
    float4 p4 = pv[i0 + 4 * NT];
    float4 p5 = pv[i0 + 5 * NT];
    float4 p6 = pv[i0 + 6 * NT];
    float4 p7 = pv[i0 + 7 * NT];
    float4 a4 = row[i0 + 4 * NT];
    float4 a5 = row[i0 + 5 * NT];
    float4 a6 = row[i0 + 6 * NT];
    float4 a7 = row[i0 + 7 * NT];

    float sum = dot4(a0, p0);
    sum += dot4(a1, p1);
    sum += dot4(a2, p2);
    sum += dot4(a3, p3);
    sum += dot4(a4, p4);
    sum += dot4(a5, p5);
    sum += dot4(a6, p6);
    sum += dot4(a7, p7);

    // warp reduce
    #pragma unroll
    for (int off = 16; off > 0; off >>= 1)
        sum += __shfl_xor_sync(0xFFFFFFFFu, sum, off);

    __shared__ float warp_sums[NT / 32];
    const int lane = threadIdx.x & 31;
    const int wid  = threadIdx.x >> 5;
    if (lane == 0) warp_sums[wid] = sum;
    __syncthreads();

    if (wid == 0) {
        float s = (lane < NT / 32) ? warp_sums[lane] : 0.0f;
        #pragma unroll
        for (int off = 16; off > 0; off >>= 1)
            s += __shfl_xor_sync(0xFFFFFFFFu, s, off);
        if (lane == 0) out[j] = s;
    }
}

extern "C" void kernel_launch(void* const* d_in, const int* in_sizes, int n_in,
                              void* d_out, int out_size)
{
    const float* X   = (const float*)d_in[0];
    const float* Y   = (const float*)d_in[1];
    const float* p   = (const float*)d_in[2];
    const int* inds1 = (const int*)d_in[3];
    const int* inds2 = (const int*)d_in[4];
    float* out       = (float*)d_out;

    gathered_dot_kernel<<<NDOTS, NT>>>(X, Y, p, inds1, inds2, out);
}